// round 12
// baseline (speedup 1.0000x reference)
#include <cuda_runtime.h>
#include <cuda_bf16.h>
#include <cstdint>
#include <math.h>

#define BATCH   4096
#define NLEAF   50000
#define DIM     256
#define CHUNKL  5556
#define NCHUNK  9
#define NTILES  44
#define EPSF    1e-7f
#define SHORTL  16
#define NSLOT   8
#define NCANDR  (NCHUNK * NSLOT * 2)   // 144 per row

// smem: 3 stages of {Xbf, Ybf} (each mat 128 rows x 144B pitch, 128B data).
// f32 key-dump buffer overlays stages 0+1; chunk(t,0) always lives in stage 2,
// so the cross-tile prefetch survives the dump/scan phase.
#define PITCH    144
#define MATB     (128 * PITCH)         // 18432
#define STAGEB   (2 * MATB)            // 36864
#define DPITCH   132                   // dump pitch in floats
#define DUMPB    (128 * DPITCH * 4)    // 67584  (<= 2*STAGEB = 73728)
#define OFF_SCL  (3 * STAGEB)          // 110592
#define SMEM_TOTAL (OFF_SCL + 128 * 8) // 111616 -> 2 CTAs/SM (223232 <= 228KB)

__device__ float g_x2[BATCH];
__device__ float g_y2[NLEAF];
__device__ float2 g_aff[NLEAF];        // (inv, y2*inv)
__device__ __align__(16) __nv_bfloat16 g_Xb[(size_t)BATCH * DIM];
__device__ __align__(16) __nv_bfloat16 g_Yb[(size_t)NLEAF * DIM];   // -2*inv*y
__device__ float g_cval[(size_t)NCHUNK * BATCH * NSLOT * 2];
__device__ int   g_cidx[(size_t)NCHUNK * BATCH * NSLOT * 2];

__device__ __forceinline__ uint32_t smem_to_u32(const void* p) {
    uint32_t a;
    asm("{ .reg .u64 t; cvta.to.shared.u64 t, %1; cvt.u32.u64 %0, t; }" : "=r"(a) : "l"(p));
    return a;
}
#define LDSM_X4(r, addr) \
    asm volatile("ldmatrix.sync.aligned.m8n8.x4.shared.b16 {%0,%1,%2,%3}, [%4];" \
        : "=r"((r)[0]), "=r"((r)[1]), "=r"((r)[2]), "=r"((r)[3]) : "r"(addr))
#define MMA16816(c, a, b0, b1) \
    asm volatile("mma.sync.aligned.m16n8k16.row.col.f32.bf16.bf16.f32 " \
        "{%0,%1,%2,%3},{%4,%5,%6,%7},{%8,%9},{%0,%1,%2,%3};" \
        : "+f"((c)[0]), "+f"((c)[1]), "+f"((c)[2]), "+f"((c)[3]) \
        : "r"((a)[0]), "r"((a)[1]), "r"((a)[2]), "r"((a)[3]), "r"(b0), "r"(b1))
#define CP_WAIT(n) asm volatile("cp.async.wait_group %0;" :: "n"(n) : "memory")

__device__ __forceinline__ unsigned bfu(__nv_bfloat16 h) {
    return (unsigned)__bfloat16_as_ushort(h);
}

// ---------------- Kernel 1: norms + single bf16 quantization --------------
// X rows: bf16(x).  Y rows: bf16(-2*inv*y), inv = 1/(1-y2).
// key = dot + x2*inv[col] + y2inv[col]: monotone hyperbolic rank key.
__global__ void prep_kernel(const float* __restrict__ X, const float* __restrict__ Y) {
    int warp = (blockIdx.x * blockDim.x + threadIdx.x) >> 5;
    int lane = threadIdx.x & 31;
    if (warp >= BATCH + NLEAF) return;
    bool isX = warp < BATCH;
    int row = isX ? warp : warp - BATCH;
    const float* src = (isX ? X : Y) + (size_t)row * DIM;
    float4 a = ((const float4*)src)[lane * 2];
    float4 b = ((const float4*)src)[lane * 2 + 1];
    float v[8] = {a.x, a.y, a.z, a.w, b.x, b.y, b.z, b.w};
    float s = 0.0f;
    #pragma unroll
    for (int i = 0; i < 8; i++) s += v[i] * v[i];
    #pragma unroll
    for (int o = 16; o; o >>= 1) s += __shfl_xor_sync(0xffffffffu, s, o);

    float sc = 1.0f;
    __nv_bfloat16* dst;
    if (isX) {
        if (lane == 0) g_x2[row] = s;
        dst = g_Xb + (size_t)row * DIM;
    } else {
        float inv = 1.0f / (1.0f - s);
        if (lane == 0) {
            g_y2[row] = s;
            g_aff[row] = make_float2(inv, s * inv);
        }
        sc = -2.0f * inv;
        dst = g_Yb + (size_t)row * DIM;
    }
    unsigned w[4];
    #pragma unroll
    for (int i = 0; i < 4; i++) {
        __nv_bfloat16 h0 = __float2bfloat16(v[2*i] * sc);
        __nv_bfloat16 h1 = __float2bfloat16(v[2*i+1] * sc);
        w[i] = bfu(h0) | (bfu(h1) << 16);
    }
    ((uint4*)dst)[lane] = make_uint4(w[0], w[1], w[2], w[3]);
}

// cp.async one 64-element (128B) k-chunk of X and Y tiles into one smem stage.
__device__ __forceinline__ void issue_loads(uint32_t stg, int tid, int mrow0,
                                            int leaf0, int kc) {
    const int k0 = kc * 64;
    #pragma unroll
    for (int i = 0; i < 8; i++) {
        int u = tid + 256 * i;
        int mat = u >> 10;
        int rem = u & 1023;
        int row = rem >> 3;
        int col = rem & 7;
        uint32_t dst = stg + (uint32_t)mat * MATB + (uint32_t)row * PITCH
                     + (uint32_t)col * 16;
        const __nv_bfloat16* src;
        if (mat == 0) {
            src = g_Xb + (size_t)(mrow0 + row) * DIM + k0 + col * 8;
        } else {
            int leaf = leaf0 + row; if (leaf >= NLEAF) leaf = NLEAF - 1;
            src = g_Yb + (size_t)leaf * DIM + k0 + col * 8;
        }
        asm volatile("cp.async.cg.shared.global [%0], [%1], 16;"
                     :: "r"(dst), "l"(src) : "memory");
    }
    asm volatile("cp.async.commit_group;" ::: "memory");
}

// ---------------- Kernel 2: single-pass bf16 mma.sync GEMM + fused top-8 --
// 256 threads = 8 warps (2m x 4n), warp tile 64x32, block tile 128x128, K=256.
// 3-stage ring, 2-deep in-flight loads mid-tile; chunk(t,0) pinned to stage 2.
__global__ void __launch_bounds__(256, 2) main_kernel() {
    extern __shared__ char smem[];
    const uint32_t sb = smem_to_u32(smem);
    const int tid = threadIdx.x, lane = tid & 31, w = tid >> 5;
    const int wm = w >> 2, wn = w & 3;
    const int mblk = blockIdx.x, chunk = blockIdx.y;
    const int mrow0 = mblk * 128;
    const int leaf_base = chunk * CHUNKL;
    int leaf_end = leaf_base + CHUNKL; if (leaf_end > NLEAF) leaf_end = NLEAF;

    const uint32_t aoff = (uint32_t)(wm * 64 + (lane & 15)) * PITCH
                        + ((lane >> 4) & 1) * 16;
    const uint32_t boff = (uint32_t)(wn * 32 + (lane & 7) + ((lane >> 4) & 1) * 8) * PITCH
                        + ((lane >> 3) & 1) * 16;

    // dump-phase row constants: x2 for the 8 rows this thread owns
    float x2r8[8];
    {
        const int rbase = mrow0 + wm * 64 + (lane >> 2);
        #pragma unroll
        for (int mi = 0; mi < 4; mi++) {
            x2r8[mi * 2]     = g_x2[rbase + mi * 16];
            x2r8[mi * 2 + 1] = g_x2[rbase + mi * 16 + 8];
        }
    }
    const uint32_t sSCL = sb + OFF_SCL;

    float tv[NSLOT]; int ti[NSLOT];
    #pragma unroll
    for (int q = 0; q < NSLOT; q++) { tv[q] = INFINITY; ti[q] = -1; }

    // prologue: chunk(0,0) -> stage2
    issue_loads(sb + 2 * STAGEB, tid, mrow0, leaf_base, 0);

    // per-kc stage map: kc0->s2, kc1->s0, kc2->s1, kc3->s2
    const uint32_t stgmap[4] = {sb + 2 * STAGEB, sb, sb + STAGEB, sb + 2 * STAGEB};

    for (int t = 0; t < NTILES; t++) {
        const int leaf0 = leaf_base + t * 128;
        // stage this tile's per-col affine terms (read at dump; prev tile's
        // dump read is separated by the post-dump sync)
        if (tid < 128) {
            int leaf = leaf0 + tid; if (leaf >= NLEAF) leaf = NLEAF - 1;
            float2 af = g_aff[leaf];
            asm volatile("st.shared.v2.f32 [%0], {%1,%2};"
                         :: "r"(sSCL + tid * 8), "f"(af.x), "f"(af.y) : "memory");
        }

        float c[4][4][4];
        #pragma unroll
        for (int mi = 0; mi < 4; mi++)
            #pragma unroll
            for (int ni = 0; ni < 4; ni++)
                #pragma unroll
                for (int e = 0; e < 4; e++) c[mi][ni][e] = 0.0f;

        #pragma unroll
        for (int kc = 0; kc < 4; kc++) {
            // wait policy: keep up to 1 younger group in flight mid-tile
            if (kc == 0 || kc == 3) { CP_WAIT(0); } else { CP_WAIT(1); }
            __syncthreads();          // all warps done reading the dst stage(s)
            if (kc == 0) {
                issue_loads(sb,          tid, mrow0, leaf0, 1);   // chunk1 -> s0
                issue_loads(sb + STAGEB, tid, mrow0, leaf0, 2);   // chunk2 -> s1
            } else if (kc == 1) {
                issue_loads(sb + 2 * STAGEB, tid, mrow0, leaf0, 3); // chunk3 -> s2
            }

            const uint32_t stg = stgmap[kc];
            #pragma unroll
            for (int ks = 0; ks < 4; ks++) {
                uint32_t a[4][4], b[2][4];
                #pragma unroll
                for (int mi = 0; mi < 4; mi++)
                    LDSM_X4(a[mi], stg + (uint32_t)(mi * 16) * PITCH + ks * 32 + aoff);
                #pragma unroll
                for (int nb = 0; nb < 2; nb++)
                    LDSM_X4(b[nb], stg + MATB + (uint32_t)(nb * 16) * PITCH + ks * 32 + boff);
                #pragma unroll
                for (int mi = 0; mi < 4; mi++) {
                    #pragma unroll
                    for (int nb = 0; nb < 2; nb++) {
                        MMA16816(c[mi][2 * nb],     a[mi], b[nb][0], b[nb][1]);
                        MMA16816(c[mi][2 * nb + 1], a[mi], b[nb][2], b[nb][3]);
                    }
                }
            }
        }
        __syncthreads();   // all warps done with stages before dump overlays s0+s1

        // cross-tile prefetch: chunk(t+1,0) -> s2 (free after kc3; flies
        // through dump+scan)
        if (t + 1 < NTILES)
            issue_loads(sb + 2 * STAGEB, tid, mrow0, leaf0 + 128, 0);

        // dump: finalize keys (dot + x2*inv + y2inv, clamped) into s0+s1
        {
            const int r0 = wm * 64 + (lane >> 2);
            const int c0 = wn * 32 + 2 * (lane & 3);
            #pragma unroll
            for (int ni = 0; ni < 4; ni++) {
                int cA = c0 + ni * 8;
                float2 sA, sB;
                asm volatile("ld.shared.v2.f32 {%0,%1}, [%2];"
                             : "=f"(sA.x), "=f"(sA.y) : "r"(sSCL + cA * 8));
                asm volatile("ld.shared.v2.f32 {%0,%1}, [%2];"
                             : "=f"(sB.x), "=f"(sB.y) : "r"(sSCL + (cA + 1) * 8));
                #pragma unroll
                for (int mi = 0; mi < 4; mi++) {
                    float k0 = fmaxf(fmaf(x2r8[2*mi],   sA.x, sA.y) + c[mi][ni][0], 0.0f);
                    float k1 = fmaxf(fmaf(x2r8[2*mi],   sB.x, sB.y) + c[mi][ni][1], 0.0f);
                    float k2 = fmaxf(fmaf(x2r8[2*mi+1], sA.x, sA.y) + c[mi][ni][2], 0.0f);
                    float k3 = fmaxf(fmaf(x2r8[2*mi+1], sB.x, sB.y) + c[mi][ni][3], 0.0f);
                    uint32_t a0 = sb + (uint32_t)((r0 + mi * 16) * DPITCH + cA) * 4;
                    asm volatile("st.shared.v2.f32 [%0], {%1,%2};"
                                 :: "r"(a0), "f"(k0), "f"(k1) : "memory");
                    asm volatile("st.shared.v2.f32 [%0], {%1,%2};"
                                 :: "r"(a0 + 8 * DPITCH * 4), "f"(k2), "f"(k3) : "memory");
                }
            }
        }
        __syncthreads();

        // scan: thread owns (row = tid&127, half = tid>>7): top-8 over 64 keys
        {
            const int half = tid >> 7;
            int nvalid = leaf_end - leaf0; if (nvalid > 128) nvalid = 128;
            const uint32_t rb = sb + (uint32_t)(tid & 127) * (DPITCH * 4) + half * 256;
            #pragma unroll 4
            for (int j4 = 0; j4 < 16; j4++) {
                float v0, v1, v2, v3;
                asm volatile("ld.shared.v4.f32 {%0,%1,%2,%3}, [%4];"
                             : "=f"(v0), "=f"(v1), "=f"(v2), "=f"(v3)
                             : "r"(rb + j4 * 16));
                float vv[4] = {v0, v1, v2, v3};
                #pragma unroll
                for (int e = 0; e < 4; e++) {
                    int col = half * 64 + j4 * 4 + e;
                    float key = vv[e];
                    if (col < nvalid && key < tv[NSLOT - 1]) {
                        tv[NSLOT - 1] = key; ti[NSLOT - 1] = leaf0 + col;
                        #pragma unroll
                        for (int q = NSLOT - 1; q > 0; q--) {
                            if (tv[q] < tv[q - 1]) {
                                float fv = tv[q]; tv[q] = tv[q - 1]; tv[q - 1] = fv;
                                int iv = ti[q]; ti[q] = ti[q - 1]; ti[q - 1] = iv;
                            }
                        }
                    }
                }
            }
        }
        __syncthreads();   // scan done before next tile's issues hit s0/s1
    }

    const int grow_s = mrow0 + (tid & 127);
    const size_t cb = (((size_t)chunk * BATCH + grow_s) * 2 + (tid >> 7)) * NSLOT;
    #pragma unroll
    for (int q = 0; q < NSLOT; q++) { g_cval[cb + q] = tv[q]; g_cidx[cb + q] = ti[q]; }
}

// ---------------- Kernel 3: merge 144 cands -> top-16, exact re-rank ------
__global__ void merge_kernel(const float* __restrict__ X, const float* __restrict__ Y,
                             const int* __restrict__ ids, const float* __restrict__ thr_p,
                             float* __restrict__ out, int out_size) {
    const int lane = threadIdx.x & 31;
    const int row = blockIdx.x * 8 + (threadIdx.x >> 5);
    if (row >= BATCH) return;
    const unsigned FULL = 0xffffffffu;

    float lv[SHORTL]; int li[SHORTL];
    #pragma unroll
    for (int s = 0; s < SHORTL; s++) { lv[s] = INFINITY; li[s] = 0x7fffffff; }
    for (int f = lane; f < NCANDR; f += 32) {
        int ch = f >> 4, r = f & 15;
        size_t a = ((size_t)ch * BATCH + row) * 16 + r;
        float v = g_cval[a];
        if (v < lv[SHORTL - 1]) {
            int ix = g_cidx[a];
            if (ix < 0) continue;
            int p = SHORTL - 1;
            while (p > 0 && (lv[p-1] > v || (lv[p-1] == v && li[p-1] > ix))) {
                lv[p] = lv[p-1]; li[p] = li[p-1]; p--;
            }
            lv[p] = v; li[p] = ix;
        }
    }

    int head = 0, seli = -1;
    for (int r = 0; r < SHORTL; r++) {
        float bv = (head < SHORTL) ? lv[head] : INFINITY;
        int   bi = (head < SHORTL) ? li[head] : 0x7fffffff;
        int   bl = lane;
        #pragma unroll
        for (int o = 16; o > 0; o >>= 1) {
            float ov = __shfl_down_sync(FULL, bv, o);
            int oi = __shfl_down_sync(FULL, bi, o);
            int ol = __shfl_down_sync(FULL, bl, o);
            if (ov < bv || (ov == bv && oi < bi)) { bv = ov; bi = oi; bl = ol; }
        }
        bi = __shfl_sync(FULL, bi, 0);
        bl = __shfl_sync(FULL, bl, 0);
        if (lane == r) seli = bi;
        if (lane == bl) head++;
    }

    float x2 = g_x2[row];
    const float4* xr = (const float4*)(X + (size_t)row * DIM);
    float4 xa = xr[lane * 2], xb = xr[lane * 2 + 1];
    float my_dist = INFINITY;
    for (int cc = 0; cc < SHORTL; cc++) {
        int ci = __shfl_sync(FULL, seli, cc);
        float dist = INFINITY;
        if (ci >= 0 && ci < NLEAF) {
            const float4* yr = (const float4*)(Y + (size_t)ci * DIM);
            float4 ya = yr[lane * 2], yb = yr[lane * 2 + 1];
            float s = xa.x*ya.x + xa.y*ya.y + xa.z*ya.z + xa.w*ya.w
                    + xb.x*yb.x + xb.y*yb.y + xb.z*yb.z + xb.w*yb.w;
            #pragma unroll
            for (int o = 16; o > 0; o >>= 1) s += __shfl_down_sync(FULL, s, o);
            s = __shfl_sync(FULL, s, 0);
            float y2 = g_y2[ci];
            float sq    = fmaxf(x2 + y2 - 2.0f * s, 0.0f);
            float denom = fmaxf((1.0f - x2) * (1.0f - y2), EPSF);
            float arg   = fmaxf(1.0f + 2.0f * sq / denom, 1.0f + EPSF);
            dist = acoshf(arg);
        } else ci = -1;
        if (lane == cc) { my_dist = dist; seli = ci; }
    }

    float dall[SHORTL]; int iall[SHORTL];
    for (int cc = 0; cc < SHORTL; cc++) {
        dall[cc] = __shfl_sync(FULL, my_dist, cc);
        iall[cc] = __shfl_sync(FULL, seli, cc);
    }
    for (int a2 = 1; a2 < SHORTL; a2++) {
        float dv = dall[a2]; int iv = iall[a2];
        int p = a2;
        while (p > 0 && (dall[p-1] > dv || (dall[p-1] == dv && iall[p-1] > iv))) {
            dall[p] = dall[p-1]; iall[p] = iall[p-1]; p--;
        }
        dall[p] = dv; iall[p] = iv;
    }

    if (lane == 0) {
        float score = dall[0];
        out[row] = score;
        if (out_size >= 2 * BATCH)
            out[BATCH + row] = (score > thr_p[0]) ? 1.0f : 0.0f;
        if (out_size >= 7 * BATCH) {
            #pragma unroll
            for (int j = 0; j < 5; j++) {
                int ci = iall[j];
                out[2 * BATCH + (size_t)row * 5 + j] = (float)((ci >= 0) ? ids[ci] : 0);
            }
        }
    }
}

// ---------------------------------------------------------------------------
extern "C" void kernel_launch(void* const* d_in, const int* in_sizes, int n_in,
                              void* d_out, int out_size) {
    const float* X   = (const float*)d_in[0];
    const float* Y   = (const float*)d_in[1];
    const int*   ids = (const int*)d_in[2];
    const float* thr = (const float*)d_in[3];
    float* out = (float*)d_out;

    cudaFuncSetAttribute(main_kernel, cudaFuncAttributeMaxDynamicSharedMemorySize,
                         SMEM_TOTAL);

    int prep_warps = BATCH + NLEAF;
    prep_kernel<<<(prep_warps + 7) / 8, 256>>>(X, Y);

    main_kernel<<<dim3(BATCH / 128, NCHUNK), 256, SMEM_TOTAL>>>();

    merge_kernel<<<BATCH / 8, 256>>>(X, Y, ids, thr, out, out_size);
}

// round 13
// speedup vs baseline: 1.0446x; 1.0446x over previous
#include <cuda_runtime.h>
#include <cuda_bf16.h>
#include <cstdint>
#include <math.h>

#define BATCH   4096
#define NLEAF   50000
#define DIM     256
#define CHUNKL  5556
#define NCHUNK  9
#define NTILES  44
#define EPSF    1e-7f
#define SHORTL  16
#define NSLOT   8
#define NCANDR  (NCHUNK * NSLOT * 2)   // 144 per row

// smem: 2 stages of {Xbf, Ybf} (each mat 128 rows x 144B pitch, 128B data).
// f32 key-dump buffer overlays STAGE 1 ONLY plus a dedicated extension, so
// stage 0 stays live across the epilogue -> next tile's first chunk can be
// prefetched during kc=3 and remain in flight through dump+scan.
#define PITCH    144
#define MATB     (128 * PITCH)         // 18432
#define STAGEB   (2 * MATB)            // 36864
#define DPITCH   132                   // dump pitch in floats
#define DUMPB    (128 * DPITCH * 4)    // 67584
#define OFF_DUMP STAGEB                // dump = stage1 (36864B) + ext (30720B)
#define OFF_SCL  (OFF_DUMP + DUMPB)    // 104448
#define SMEM_TOTAL (OFF_SCL + 128 * 8) // 105472 -> 2 CTAs/SM

__device__ float g_x2[BATCH];
__device__ float g_y2[NLEAF];
__device__ float2 g_aff[NLEAF];        // (inv, y2*inv)
__device__ __align__(16) __nv_bfloat16 g_Xb[(size_t)BATCH * DIM];
__device__ __align__(16) __nv_bfloat16 g_Yb[(size_t)NLEAF * DIM];   // -2*inv*y
__device__ float g_cval[(size_t)NCHUNK * BATCH * NSLOT * 2];
__device__ int   g_cidx[(size_t)NCHUNK * BATCH * NSLOT * 2];

__device__ __forceinline__ uint32_t smem_to_u32(const void* p) {
    uint32_t a;
    asm("{ .reg .u64 t; cvta.to.shared.u64 t, %1; cvt.u32.u64 %0, t; }" : "=r"(a) : "l"(p));
    return a;
}
#define LDSM_X4(r, addr) \
    asm volatile("ldmatrix.sync.aligned.m8n8.x4.shared.b16 {%0,%1,%2,%3}, [%4];" \
        : "=r"((r)[0]), "=r"((r)[1]), "=r"((r)[2]), "=r"((r)[3]) : "r"(addr))
#define MMA16816(c, a, b0, b1) \
    asm volatile("mma.sync.aligned.m16n8k16.row.col.f32.bf16.bf16.f32 " \
        "{%0,%1,%2,%3},{%4,%5,%6,%7},{%8,%9},{%0,%1,%2,%3};" \
        : "+f"((c)[0]), "+f"((c)[1]), "+f"((c)[2]), "+f"((c)[3]) \
        : "r"((a)[0]), "r"((a)[1]), "r"((a)[2]), "r"((a)[3]), "r"(b0), "r"(b1))
#define CP_WAIT(n) asm volatile("cp.async.wait_group %0;" :: "n"(n) : "memory")

__device__ __forceinline__ unsigned bfu(__nv_bfloat16 h) {
    return (unsigned)__bfloat16_as_ushort(h);
}

// ---------------- Kernel 1: norms + single bf16 quantization --------------
// X rows: bf16(x).  Y rows: bf16(-2*inv*y), inv = 1/(1-y2).
// key = dot + x2*inv[col] + y2inv[col]: monotone hyperbolic rank key.
__global__ void prep_kernel(const float* __restrict__ X, const float* __restrict__ Y) {
    int warp = (blockIdx.x * blockDim.x + threadIdx.x) >> 5;
    int lane = threadIdx.x & 31;
    if (warp >= BATCH + NLEAF) return;
    bool isX = warp < BATCH;
    int row = isX ? warp : warp - BATCH;
    const float* src = (isX ? X : Y) + (size_t)row * DIM;
    float4 a = ((const float4*)src)[lane * 2];
    float4 b = ((const float4*)src)[lane * 2 + 1];
    float v[8] = {a.x, a.y, a.z, a.w, b.x, b.y, b.z, b.w};
    float s = 0.0f;
    #pragma unroll
    for (int i = 0; i < 8; i++) s += v[i] * v[i];
    #pragma unroll
    for (int o = 16; o; o >>= 1) s += __shfl_xor_sync(0xffffffffu, s, o);

    float sc = 1.0f;
    __nv_bfloat16* dst;
    if (isX) {
        if (lane == 0) g_x2[row] = s;
        dst = g_Xb + (size_t)row * DIM;
    } else {
        float inv = 1.0f / (1.0f - s);
        if (lane == 0) {
            g_y2[row] = s;
            g_aff[row] = make_float2(inv, s * inv);
        }
        sc = -2.0f * inv;
        dst = g_Yb + (size_t)row * DIM;
    }
    unsigned w[4];
    #pragma unroll
    for (int i = 0; i < 4; i++) {
        __nv_bfloat16 h0 = __float2bfloat16(v[2*i] * sc);
        __nv_bfloat16 h1 = __float2bfloat16(v[2*i+1] * sc);
        w[i] = bfu(h0) | (bfu(h1) << 16);
    }
    ((uint4*)dst)[lane] = make_uint4(w[0], w[1], w[2], w[3]);
}

// cp.async one 64-element (128B) k-chunk of X and Y tiles into one smem stage.
__device__ __forceinline__ void issue_loads(uint32_t stg, int tid, int mrow0,
                                            int leaf0, int kc) {
    const int k0 = kc * 64;
    #pragma unroll
    for (int i = 0; i < 8; i++) {
        int u = tid + 256 * i;
        int mat = u >> 10;
        int rem = u & 1023;
        int row = rem >> 3;
        int col = rem & 7;
        uint32_t dst = stg + (uint32_t)mat * MATB + (uint32_t)row * PITCH
                     + (uint32_t)col * 16;
        const __nv_bfloat16* src;
        if (mat == 0) {
            src = g_Xb + (size_t)(mrow0 + row) * DIM + k0 + col * 8;
        } else {
            int leaf = leaf0 + row; if (leaf >= NLEAF) leaf = NLEAF - 1;
            src = g_Yb + (size_t)leaf * DIM + k0 + col * 8;
        }
        asm volatile("cp.async.cg.shared.global [%0], [%1], 16;"
                     :: "r"(dst), "l"(src) : "memory");
    }
    asm volatile("cp.async.commit_group;" ::: "memory");
}

// ---------------- Kernel 2: single-pass bf16 mma.sync GEMM + fused top-8 --
// 256 threads = 8 warps (2m x 4n), warp tile 64x32, block tile 128x128, K=256.
// Cross-tile prefetch into stage0 (not overlaid by the dump). 6 syncs/tile:
// the post-scan sync is subsumed by next tile's kc0 CP_WAIT(0)+sync (the only
// writer of the scanned region is kc0's issue into stage1, after that sync).
__global__ void __launch_bounds__(256, 2) main_kernel() {
    extern __shared__ char smem[];
    const uint32_t sb = smem_to_u32(smem);
    const int tid = threadIdx.x, lane = tid & 31, w = tid >> 5;
    const int wm = w >> 2, wn = w & 3;
    const int mblk = blockIdx.x, chunk = blockIdx.y;
    const int mrow0 = mblk * 128;
    const int leaf_base = chunk * CHUNKL;
    int leaf_end = leaf_base + CHUNKL; if (leaf_end > NLEAF) leaf_end = NLEAF;

    const uint32_t aoff = (uint32_t)(wm * 64 + (lane & 15)) * PITCH
                        + ((lane >> 4) & 1) * 16;
    const uint32_t boff = (uint32_t)(wn * 32 + (lane & 7) + ((lane >> 4) & 1) * 8) * PITCH
                        + ((lane >> 3) & 1) * 16;

    // dump-phase row constants: x2 for the 8 rows this thread owns
    float x2r8[8];
    {
        const int rbase = mrow0 + wm * 64 + (lane >> 2);
        #pragma unroll
        for (int mi = 0; mi < 4; mi++) {
            x2r8[mi * 2]     = g_x2[rbase + mi * 16];
            x2r8[mi * 2 + 1] = g_x2[rbase + mi * 16 + 8];
        }
    }
    const uint32_t sSCL = sb + OFF_SCL;

    float tv[NSLOT]; int ti[NSLOT];
    #pragma unroll
    for (int q = 0; q < NSLOT; q++) { tv[q] = INFINITY; ti[q] = -1; }

    // prologue: chunk(0,0) -> stage0
    issue_loads(sb, tid, mrow0, leaf_base, 0);

    for (int t = 0; t < NTILES; t++) {
        const int leaf0 = leaf_base + t * 128;
        // stage this tile's per-col affine terms (read at this tile's dump;
        // prev dump's read of sSCL is ordered by the pre-scan sync)
        if (tid < 128) {
            int leaf = leaf0 + tid; if (leaf >= NLEAF) leaf = NLEAF - 1;
            float2 af = g_aff[leaf];
            asm volatile("st.shared.v2.f32 [%0], {%1,%2};"
                         :: "r"(sSCL + tid * 8), "f"(af.x), "f"(af.y) : "memory");
        }

        float c[4][4][4];
        #pragma unroll
        for (int mi = 0; mi < 4; mi++)
            #pragma unroll
            for (int ni = 0; ni < 4; ni++)
                #pragma unroll
                for (int e = 0; e < 4; e++) c[mi][ni][e] = 0.0f;

        #pragma unroll
        for (int kc = 0; kc < 4; kc++) {
            CP_WAIT(0);               // chunk(t,kc) resident in stage kc&1
            __syncthreads();          // all warps done reading the dst stage
                                      // (at kc0: also orders prev scan before
                                      //  the issue into stage1 below)
            if (kc < 3) {
                issue_loads(sb + (uint32_t)((kc + 1) & 1) * STAGEB,
                            tid, mrow0, leaf0, kc + 1);
            } else if (t + 1 < NTILES) {
                // cross-tile prefetch into stage0 (not overlaid by dump)
                issue_loads(sb, tid, mrow0, leaf0 + 128, 0);
            }

            const uint32_t stg = sb + (uint32_t)(kc & 1) * STAGEB;
            #pragma unroll
            for (int ks = 0; ks < 4; ks++) {
                uint32_t a[4][4], b[2][4];
                #pragma unroll
                for (int mi = 0; mi < 4; mi++)
                    LDSM_X4(a[mi], stg + (uint32_t)(mi * 16) * PITCH + ks * 32 + aoff);
                #pragma unroll
                for (int nb = 0; nb < 2; nb++)
                    LDSM_X4(b[nb], stg + MATB + (uint32_t)(nb * 16) * PITCH + ks * 32 + boff);
                #pragma unroll
                for (int mi = 0; mi < 4; mi++) {
                    #pragma unroll
                    for (int nb = 0; nb < 2; nb++) {
                        MMA16816(c[mi][2 * nb],     a[mi], b[nb][0], b[nb][1]);
                        MMA16816(c[mi][2 * nb + 1], a[mi], b[nb][2], b[nb][3]);
                    }
                }
            }
        }
        __syncthreads();   // all warps done reading stage1 before dump overlays it

        // dump: finalize keys (dot + x2*inv + y2inv, clamped) into
        // stage1 + extension (stage0 holds the in-flight prefetch)
        {
            const int r0 = wm * 64 + (lane >> 2);
            const int c0 = wn * 32 + 2 * (lane & 3);
            #pragma unroll
            for (int ni = 0; ni < 4; ni++) {
                int cA = c0 + ni * 8;
                float2 sA, sB;
                asm volatile("ld.shared.v2.f32 {%0,%1}, [%2];"
                             : "=f"(sA.x), "=f"(sA.y) : "r"(sSCL + cA * 8));
                asm volatile("ld.shared.v2.f32 {%0,%1}, [%2];"
                             : "=f"(sB.x), "=f"(sB.y) : "r"(sSCL + (cA + 1) * 8));
                #pragma unroll
                for (int mi = 0; mi < 4; mi++) {
                    float k0 = fmaxf(fmaf(x2r8[2*mi],   sA.x, sA.y) + c[mi][ni][0], 0.0f);
                    float k1 = fmaxf(fmaf(x2r8[2*mi],   sB.x, sB.y) + c[mi][ni][1], 0.0f);
                    float k2 = fmaxf(fmaf(x2r8[2*mi+1], sA.x, sA.y) + c[mi][ni][2], 0.0f);
                    float k3 = fmaxf(fmaf(x2r8[2*mi+1], sB.x, sB.y) + c[mi][ni][3], 0.0f);
                    uint32_t a0 = sb + OFF_DUMP
                                + (uint32_t)((r0 + mi * 16) * DPITCH + cA) * 4;
                    asm volatile("st.shared.v2.f32 [%0], {%1,%2};"
                                 :: "r"(a0), "f"(k0), "f"(k1) : "memory");
                    asm volatile("st.shared.v2.f32 [%0], {%1,%2};"
                                 :: "r"(a0 + 8 * DPITCH * 4), "f"(k2), "f"(k3) : "memory");
                }
            }
        }
        __syncthreads();

        // scan: thread owns (row = tid&127, half = tid>>7): top-8 over 64 keys
        {
            const int half = tid >> 7;
            int nvalid = leaf_end - leaf0; if (nvalid > 128) nvalid = 128;
            const uint32_t rb = sb + OFF_DUMP + (uint32_t)(tid & 127) * (DPITCH * 4)
                              + half * 256;
            #pragma unroll 4
            for (int j4 = 0; j4 < 16; j4++) {
                float v0, v1, v2, v3;
                asm volatile("ld.shared.v4.f32 {%0,%1,%2,%3}, [%4];"
                             : "=f"(v0), "=f"(v1), "=f"(v2), "=f"(v3)
                             : "r"(rb + j4 * 16));
                float vv[4] = {v0, v1, v2, v3};
                #pragma unroll
                for (int e = 0; e < 4; e++) {
                    int col = half * 64 + j4 * 4 + e;
                    float key = vv[e];
                    if (col < nvalid && key < tv[NSLOT - 1]) {
                        tv[NSLOT - 1] = key; ti[NSLOT - 1] = leaf0 + col;
                        #pragma unroll
                        for (int q = NSLOT - 1; q > 0; q--) {
                            if (tv[q] < tv[q - 1]) {
                                float fv = tv[q]; tv[q] = tv[q - 1]; tv[q - 1] = fv;
                                int iv = ti[q]; ti[q] = ti[q - 1]; ti[q - 1] = iv;
                            }
                        }
                    }
                }
            }
        }
        // NOTE: no post-scan sync — next tile's kc0 CP_WAIT(0)+__syncthreads
        // orders this scan before any write to the scanned region (stage1).
    }

    const int grow_s = mrow0 + (tid & 127);
    const size_t cb = (((size_t)chunk * BATCH + grow_s) * 2 + (tid >> 7)) * NSLOT;
    #pragma unroll
    for (int q = 0; q < NSLOT; q++) { g_cval[cb + q] = tv[q]; g_cidx[cb + q] = ti[q]; }
}

// ---------------- Kernel 3: merge 144 cands -> top-16, exact re-rank ------
__global__ void merge_kernel(const float* __restrict__ X, const float* __restrict__ Y,
                             const int* __restrict__ ids, const float* __restrict__ thr_p,
                             float* __restrict__ out, int out_size) {
    const int lane = threadIdx.x & 31;
    const int row = blockIdx.x * 8 + (threadIdx.x >> 5);
    if (row >= BATCH) return;
    const unsigned FULL = 0xffffffffu;

    float lv[SHORTL]; int li[SHORTL];
    #pragma unroll
    for (int s = 0; s < SHORTL; s++) { lv[s] = INFINITY; li[s] = 0x7fffffff; }
    for (int f = lane; f < NCANDR; f += 32) {
        int ch = f >> 4, r = f & 15;
        size_t a = ((size_t)ch * BATCH + row) * 16 + r;
        float v = g_cval[a];
        if (v < lv[SHORTL - 1]) {
            int ix = g_cidx[a];
            if (ix < 0) continue;
            int p = SHORTL - 1;
            while (p > 0 && (lv[p-1] > v || (lv[p-1] == v && li[p-1] > ix))) {
                lv[p] = lv[p-1]; li[p] = li[p-1]; p--;
            }
            lv[p] = v; li[p] = ix;
        }
    }

    int head = 0, seli = -1;
    for (int r = 0; r < SHORTL; r++) {
        float bv = (head < SHORTL) ? lv[head] : INFINITY;
        int   bi = (head < SHORTL) ? li[head] : 0x7fffffff;
        int   bl = lane;
        #pragma unroll
        for (int o = 16; o > 0; o >>= 1) {
            float ov = __shfl_down_sync(FULL, bv, o);
            int oi = __shfl_down_sync(FULL, bi, o);
            int ol = __shfl_down_sync(FULL, bl, o);
            if (ov < bv || (ov == bv && oi < bi)) { bv = ov; bi = oi; bl = ol; }
        }
        bi = __shfl_sync(FULL, bi, 0);
        bl = __shfl_sync(FULL, bl, 0);
        if (lane == r) seli = bi;
        if (lane == bl) head++;
    }

    float x2 = g_x2[row];
    const float4* xr = (const float4*)(X + (size_t)row * DIM);
    float4 xa = xr[lane * 2], xb = xr[lane * 2 + 1];
    float my_dist = INFINITY;
    for (int cc = 0; cc < SHORTL; cc++) {
        int ci = __shfl_sync(FULL, seli, cc);
        float dist = INFINITY;
        if (ci >= 0 && ci < NLEAF) {
            const float4* yr = (const float4*)(Y + (size_t)ci * DIM);
            float4 ya = yr[lane * 2], yb = yr[lane * 2 + 1];
            float s = xa.x*ya.x + xa.y*ya.y + xa.z*ya.z + xa.w*ya.w
                    + xb.x*yb.x + xb.y*yb.y + xb.z*yb.z + xb.w*yb.w;
            #pragma unroll
            for (int o = 16; o > 0; o >>= 1) s += __shfl_down_sync(FULL, s, o);
            s = __shfl_sync(FULL, s, 0);
            float y2 = g_y2[ci];
            float sq    = fmaxf(x2 + y2 - 2.0f * s, 0.0f);
            float denom = fmaxf((1.0f - x2) * (1.0f - y2), EPSF);
            float arg   = fmaxf(1.0f + 2.0f * sq / denom, 1.0f + EPSF);
            dist = acoshf(arg);
        } else ci = -1;
        if (lane == cc) { my_dist = dist; seli = ci; }
    }

    float dall[SHORTL]; int iall[SHORTL];
    for (int cc = 0; cc < SHORTL; cc++) {
        dall[cc] = __shfl_sync(FULL, my_dist, cc);
        iall[cc] = __shfl_sync(FULL, seli, cc);
    }
    for (int a2 = 1; a2 < SHORTL; a2++) {
        float dv = dall[a2]; int iv = iall[a2];
        int p = a2;
        while (p > 0 && (dall[p-1] > dv || (dall[p-1] == dv && iall[p-1] > iv))) {
            dall[p] = dall[p-1]; iall[p] = iall[p-1]; p--;
        }
        dall[p] = dv; iall[p] = iv;
    }

    if (lane == 0) {
        float score = dall[0];
        out[row] = score;
        if (out_size >= 2 * BATCH)
            out[BATCH + row] = (score > thr_p[0]) ? 1.0f : 0.0f;
        if (out_size >= 7 * BATCH) {
            #pragma unroll
            for (int j = 0; j < 5; j++) {
                int ci = iall[j];
                out[2 * BATCH + (size_t)row * 5 + j] = (float)((ci >= 0) ? ids[ci] : 0);
            }
        }
    }
}

// ---------------------------------------------------------------------------
extern "C" void kernel_launch(void* const* d_in, const int* in_sizes, int n_in,
                              void* d_out, int out_size) {
    const float* X   = (const float*)d_in[0];
    const float* Y   = (const float*)d_in[1];
    const int*   ids = (const int*)d_in[2];
    const float* thr = (const float*)d_in[3];
    float* out = (float*)d_out;

    cudaFuncSetAttribute(main_kernel, cudaFuncAttributeMaxDynamicSharedMemorySize,
                         SMEM_TOTAL);

    int prep_warps = BATCH + NLEAF;
    prep_kernel<<<(prep_warps + 7) / 8, 256>>>(X, Y);

    main_kernel<<<dim3(BATCH / 128, NCHUNK), 256, SMEM_TOTAL>>>();

    merge_kernel<<<BATCH / 8, 256>>>(X, Y, ids, thr, out, out_size);
}

// round 14
// speedup vs baseline: 1.1627x; 1.1131x over previous
#include <cuda_runtime.h>
#include <cuda_bf16.h>
#include <cstdint>
#include <math.h>

#define BATCH   4096
#define NLEAF   50000
#define DIM     256
#define CHUNKL  5556
#define NCHUNK  9
#define NTILES  44
#define EPSF    1e-7f
#define SHORTL  16
#define NSLOT   6
#define NCANDR  (NCHUNK * NSLOT * 2)   // 108 per row

// smem: 2 stages of {Xbf, Ybf} (each mat 128 rows x 144B pitch, 128B data).
// f32 key-dump buffer overlays STAGE 1 ONLY plus a dedicated extension, so
// stage 0 stays live across the epilogue -> next tile's first chunk can be
// prefetched during kc=3 and remain in flight through dump+scan.
#define PITCH    144
#define MATB     (128 * PITCH)         // 18432
#define STAGEB   (2 * MATB)            // 36864
#define DPITCH   132                   // dump pitch in floats
#define DUMPB    (128 * DPITCH * 4)    // 67584
#define OFF_DUMP STAGEB                // dump = stage1 (36864B) + ext (30720B)
#define OFF_SCL  (OFF_DUMP + DUMPB)    // 104448
#define SMEM_TOTAL (OFF_SCL + 128 * 8) // 105472 -> 2 CTAs/SM

__device__ float g_x2[BATCH];
__device__ float g_y2[NLEAF];
__device__ float2 g_aff[NLEAF];        // (inv, y2*inv)
__device__ __align__(16) __nv_bfloat16 g_Xb[(size_t)BATCH * DIM];
__device__ __align__(16) __nv_bfloat16 g_Yb[(size_t)NLEAF * DIM];   // -2*inv*y
__device__ float g_cval[(size_t)NCHUNK * BATCH * NSLOT * 2];
__device__ int   g_cidx[(size_t)NCHUNK * BATCH * NSLOT * 2];

__device__ __forceinline__ uint32_t smem_to_u32(const void* p) {
    uint32_t a;
    asm("{ .reg .u64 t; cvta.to.shared.u64 t, %1; cvt.u32.u64 %0, t; }" : "=r"(a) : "l"(p));
    return a;
}
#define LDSM_X4(r, addr) \
    asm volatile("ldmatrix.sync.aligned.m8n8.x4.shared.b16 {%0,%1,%2,%3}, [%4];" \
        : "=r"((r)[0]), "=r"((r)[1]), "=r"((r)[2]), "=r"((r)[3]) : "r"(addr))
#define MMA16816(c, a, b0, b1) \
    asm volatile("mma.sync.aligned.m16n8k16.row.col.f32.bf16.bf16.f32 " \
        "{%0,%1,%2,%3},{%4,%5,%6,%7},{%8,%9},{%0,%1,%2,%3};" \
        : "+f"((c)[0]), "+f"((c)[1]), "+f"((c)[2]), "+f"((c)[3]) \
        : "r"((a)[0]), "r"((a)[1]), "r"((a)[2]), "r"((a)[3]), "r"(b0), "r"(b1))
#define CP_WAIT(n) asm volatile("cp.async.wait_group %0;" :: "n"(n) : "memory")

__device__ __forceinline__ unsigned bfu(__nv_bfloat16 h) {
    return (unsigned)__bfloat16_as_ushort(h);
}

// ---------------- Kernel 1: norms + single bf16 quantization --------------
// X rows: bf16(x).  Y rows: bf16(-2*inv*y), inv = 1/(1-y2).
// key = dot + x2*inv[col] + y2inv[col]: monotone hyperbolic rank key.
__global__ void prep_kernel(const float* __restrict__ X, const float* __restrict__ Y) {
    int warp = (blockIdx.x * blockDim.x + threadIdx.x) >> 5;
    int lane = threadIdx.x & 31;
    if (warp >= BATCH + NLEAF) return;
    bool isX = warp < BATCH;
    int row = isX ? warp : warp - BATCH;
    const float* src = (isX ? X : Y) + (size_t)row * DIM;
    float4 a = ((const float4*)src)[lane * 2];
    float4 b = ((const float4*)src)[lane * 2 + 1];
    float v[8] = {a.x, a.y, a.z, a.w, b.x, b.y, b.z, b.w};
    float s = 0.0f;
    #pragma unroll
    for (int i = 0; i < 8; i++) s += v[i] * v[i];
    #pragma unroll
    for (int o = 16; o; o >>= 1) s += __shfl_xor_sync(0xffffffffu, s, o);

    float sc = 1.0f;
    __nv_bfloat16* dst;
    if (isX) {
        if (lane == 0) g_x2[row] = s;
        dst = g_Xb + (size_t)row * DIM;
    } else {
        float inv = 1.0f / (1.0f - s);
        if (lane == 0) {
            g_y2[row] = s;
            g_aff[row] = make_float2(inv, s * inv);
        }
        sc = -2.0f * inv;
        dst = g_Yb + (size_t)row * DIM;
    }
    unsigned w[4];
    #pragma unroll
    for (int i = 0; i < 4; i++) {
        __nv_bfloat16 h0 = __float2bfloat16(v[2*i] * sc);
        __nv_bfloat16 h1 = __float2bfloat16(v[2*i+1] * sc);
        w[i] = bfu(h0) | (bfu(h1) << 16);
    }
    ((uint4*)dst)[lane] = make_uint4(w[0], w[1], w[2], w[3]);
}

// cp.async one 64-element (128B) k-chunk of X and Y tiles into one smem stage.
__device__ __forceinline__ void issue_loads(uint32_t stg, int tid, int mrow0,
                                            int leaf0, int kc) {
    const int k0 = kc * 64;
    #pragma unroll
    for (int i = 0; i < 8; i++) {
        int u = tid + 256 * i;
        int mat = u >> 10;
        int rem = u & 1023;
        int row = rem >> 3;
        int col = rem & 7;
        uint32_t dst = stg + (uint32_t)mat * MATB + (uint32_t)row * PITCH
                     + (uint32_t)col * 16;
        const __nv_bfloat16* src;
        if (mat == 0) {
            src = g_Xb + (size_t)(mrow0 + row) * DIM + k0 + col * 8;
        } else {
            int leaf = leaf0 + row; if (leaf >= NLEAF) leaf = NLEAF - 1;
            src = g_Yb + (size_t)leaf * DIM + k0 + col * 8;
        }
        asm volatile("cp.async.cg.shared.global [%0], [%1], 16;"
                     :: "r"(dst), "l"(src) : "memory");
    }
    asm volatile("cp.async.commit_group;" ::: "memory");
}

// ---------------- Kernel 2: single-pass bf16 mma.sync GEMM + fused top-6 --
// 256 threads = 8 warps (2m x 4n), warp tile 64x32, block tile 128x128, K=256.
__global__ void __launch_bounds__(256, 2) main_kernel() {
    extern __shared__ char smem[];
    const uint32_t sb = smem_to_u32(smem);
    const int tid = threadIdx.x, lane = tid & 31, w = tid >> 5;
    const int wm = w >> 2, wn = w & 3;
    const int mblk = blockIdx.x, chunk = blockIdx.y;
    const int mrow0 = mblk * 128;
    const int leaf_base = chunk * CHUNKL;
    int leaf_end = leaf_base + CHUNKL; if (leaf_end > NLEAF) leaf_end = NLEAF;

    const uint32_t aoff = (uint32_t)(wm * 64 + (lane & 15)) * PITCH
                        + ((lane >> 4) & 1) * 16;
    const uint32_t boff = (uint32_t)(wn * 32 + (lane & 7) + ((lane >> 4) & 1) * 8) * PITCH
                        + ((lane >> 3) & 1) * 16;

    // dump-phase row constants: x2 for the 8 rows this thread owns
    float x2r8[8];
    {
        const int rbase = mrow0 + wm * 64 + (lane >> 2);
        #pragma unroll
        for (int mi = 0; mi < 4; mi++) {
            x2r8[mi * 2]     = g_x2[rbase + mi * 16];
            x2r8[mi * 2 + 1] = g_x2[rbase + mi * 16 + 8];
        }
    }
    const uint32_t sSCL = sb + OFF_SCL;

    float tv[NSLOT]; int ti[NSLOT];
    #pragma unroll
    for (int q = 0; q < NSLOT; q++) { tv[q] = INFINITY; ti[q] = -1; }

    // prologue: chunk(0,0) -> stage0
    issue_loads(sb, tid, mrow0, leaf_base, 0);

    for (int t = 0; t < NTILES; t++) {
        const int leaf0 = leaf_base + t * 128;
        // stage this tile's per-col affine terms (read at this tile's dump;
        // prev dump's read of sSCL is ordered by the pre-scan sync)
        if (tid < 128) {
            int leaf = leaf0 + tid; if (leaf >= NLEAF) leaf = NLEAF - 1;
            float2 af = g_aff[leaf];
            asm volatile("st.shared.v2.f32 [%0], {%1,%2};"
                         :: "r"(sSCL + tid * 8), "f"(af.x), "f"(af.y) : "memory");
        }

        float c[4][4][4];
        #pragma unroll
        for (int mi = 0; mi < 4; mi++)
            #pragma unroll
            for (int ni = 0; ni < 4; ni++)
                #pragma unroll
                for (int e = 0; e < 4; e++) c[mi][ni][e] = 0.0f;

        #pragma unroll
        for (int kc = 0; kc < 4; kc++) {
            CP_WAIT(0);               // chunk(t,kc) resident in stage kc&1
            __syncthreads();          // all warps done reading the dst stage
            if (kc < 3) {
                issue_loads(sb + (uint32_t)((kc + 1) & 1) * STAGEB,
                            tid, mrow0, leaf0, kc + 1);
            } else if (t + 1 < NTILES) {
                // cross-tile prefetch into stage0 (not overlaid by dump)
                issue_loads(sb, tid, mrow0, leaf0 + 128, 0);
            }

            const uint32_t stg = sb + (uint32_t)(kc & 1) * STAGEB;
            #pragma unroll
            for (int ks = 0; ks < 4; ks++) {
                uint32_t a[4][4], b[2][4];
                #pragma unroll
                for (int mi = 0; mi < 4; mi++)
                    LDSM_X4(a[mi], stg + (uint32_t)(mi * 16) * PITCH + ks * 32 + aoff);
                #pragma unroll
                for (int nb = 0; nb < 2; nb++)
                    LDSM_X4(b[nb], stg + MATB + (uint32_t)(nb * 16) * PITCH + ks * 32 + boff);
                #pragma unroll
                for (int mi = 0; mi < 4; mi++) {
                    #pragma unroll
                    for (int nb = 0; nb < 2; nb++) {
                        MMA16816(c[mi][2 * nb],     a[mi], b[nb][0], b[nb][1]);
                        MMA16816(c[mi][2 * nb + 1], a[mi], b[nb][2], b[nb][3]);
                    }
                }
            }
        }
        __syncthreads();   // all warps done reading stage1 before dump overlays it

        // dump: finalize keys (dot + x2*inv + y2inv, clamped) into
        // stage1 + extension (stage0 holds the in-flight prefetch)
        {
            const int r0 = wm * 64 + (lane >> 2);
            const int c0 = wn * 32 + 2 * (lane & 3);
            #pragma unroll
            for (int ni = 0; ni < 4; ni++) {
                int cA = c0 + ni * 8;
                float2 sA, sB;
                asm volatile("ld.shared.v2.f32 {%0,%1}, [%2];"
                             : "=f"(sA.x), "=f"(sA.y) : "r"(sSCL + cA * 8));
                asm volatile("ld.shared.v2.f32 {%0,%1}, [%2];"
                             : "=f"(sB.x), "=f"(sB.y) : "r"(sSCL + (cA + 1) * 8));
                #pragma unroll
                for (int mi = 0; mi < 4; mi++) {
                    float k0 = fmaxf(fmaf(x2r8[2*mi],   sA.x, sA.y) + c[mi][ni][0], 0.0f);
                    float k1 = fmaxf(fmaf(x2r8[2*mi],   sB.x, sB.y) + c[mi][ni][1], 0.0f);
                    float k2 = fmaxf(fmaf(x2r8[2*mi+1], sA.x, sA.y) + c[mi][ni][2], 0.0f);
                    float k3 = fmaxf(fmaf(x2r8[2*mi+1], sB.x, sB.y) + c[mi][ni][3], 0.0f);
                    uint32_t a0 = sb + OFF_DUMP
                                + (uint32_t)((r0 + mi * 16) * DPITCH + cA) * 4;
                    asm volatile("st.shared.v2.f32 [%0], {%1,%2};"
                                 :: "r"(a0), "f"(k0), "f"(k1) : "memory");
                    asm volatile("st.shared.v2.f32 [%0], {%1,%2};"
                                 :: "r"(a0 + 8 * DPITCH * 4), "f"(k2), "f"(k3) : "memory");
                }
            }
        }
        __syncthreads();

        // scan: thread owns (row = tid&127, half = tid>>7): top-6 over 64 keys
        {
            const int half = tid >> 7;
            int nvalid = leaf_end - leaf0; if (nvalid > 128) nvalid = 128;
            const uint32_t rb = sb + OFF_DUMP + (uint32_t)(tid & 127) * (DPITCH * 4)
                              + half * 256;
            float worst = tv[NSLOT - 1];
            #pragma unroll 4
            for (int j4 = 0; j4 < 16; j4++) {
                float v0, v1, v2, v3;
                asm volatile("ld.shared.v4.f32 {%0,%1,%2,%3}, [%4];"
                             : "=f"(v0), "=f"(v1), "=f"(v2), "=f"(v3)
                             : "r"(rb + j4 * 16));
                float vv[4] = {v0, v1, v2, v3};
                #pragma unroll
                for (int e = 0; e < 4; e++) {
                    int col = half * 64 + j4 * 4 + e;
                    float key = vv[e];
                    if (col < nvalid && key < worst) {
                        tv[NSLOT - 1] = key; ti[NSLOT - 1] = leaf0 + col;
                        #pragma unroll
                        for (int q = NSLOT - 1; q > 0; q--) {
                            if (tv[q] < tv[q - 1]) {
                                float fv = tv[q]; tv[q] = tv[q - 1]; tv[q - 1] = fv;
                                int iv = ti[q]; ti[q] = ti[q - 1]; ti[q - 1] = iv;
                            }
                        }
                        worst = tv[NSLOT - 1];
                    }
                }
            }
        }
        // no post-scan sync: next tile's kc0 CP_WAIT(0)+__syncthreads orders
        // this scan before any write to the scanned region (stage1).
    }

    const int grow_s = mrow0 + (tid & 127);
    const size_t cb = (((size_t)chunk * BATCH + grow_s) * 2 + (tid >> 7)) * NSLOT;
    #pragma unroll
    for (int q = 0; q < NSLOT; q++) { g_cval[cb + q] = tv[q]; g_cidx[cb + q] = ti[q]; }
}

// ---------------- Kernel 3: merge 108 cands -> top-16, exact re-rank ------
__global__ void merge_kernel(const float* __restrict__ X, const float* __restrict__ Y,
                             const int* __restrict__ ids, const float* __restrict__ thr_p,
                             float* __restrict__ out, int out_size) {
    const int lane = threadIdx.x & 31;
    const int row = blockIdx.x * 8 + (threadIdx.x >> 5);
    if (row >= BATCH) return;
    const unsigned FULL = 0xffffffffu;

    float lv[SHORTL]; int li[SHORTL];
    #pragma unroll
    for (int s = 0; s < SHORTL; s++) { lv[s] = INFINITY; li[s] = 0x7fffffff; }
    const int RSTRIDE = NSLOT * 2;   // 12 candidates per (chunk,row)
    for (int f = lane; f < NCANDR; f += 32) {
        int ch = f / RSTRIDE, r = f - ch * RSTRIDE;
        size_t a = ((size_t)ch * BATCH + row) * RSTRIDE + r;
        float v = g_cval[a];
        if (v < lv[SHORTL - 1]) {
            int ix = g_cidx[a];
            if (ix < 0) continue;
            int p = SHORTL - 1;
            while (p > 0 && (lv[p-1] > v || (lv[p-1] == v && li[p-1] > ix))) {
                lv[p] = lv[p-1]; li[p] = li[p-1]; p--;
            }
            lv[p] = v; li[p] = ix;
        }
    }

    int head = 0, seli = -1;
    for (int r = 0; r < SHORTL; r++) {
        float bv = (head < SHORTL) ? lv[head] : INFINITY;
        int   bi = (head < SHORTL) ? li[head] : 0x7fffffff;
        int   bl = lane;
        #pragma unroll
        for (int o = 16; o > 0; o >>= 1) {
            float ov = __shfl_down_sync(FULL, bv, o);
            int oi = __shfl_down_sync(FULL, bi, o);
            int ol = __shfl_down_sync(FULL, bl, o);
            if (ov < bv || (ov == bv && oi < bi)) { bv = ov; bi = oi; bl = ol; }
        }
        bi = __shfl_sync(FULL, bi, 0);
        bl = __shfl_sync(FULL, bl, 0);
        if (lane == r) seli = bi;
        if (lane == bl) head++;
    }

    float x2 = g_x2[row];
    const float4* xr = (const float4*)(X + (size_t)row * DIM);
    float4 xa = xr[lane * 2], xb = xr[lane * 2 + 1];
    float my_dist = INFINITY;
    for (int cc = 0; cc < SHORTL; cc++) {
        int ci = __shfl_sync(FULL, seli, cc);
        float dist = INFINITY;
        if (ci >= 0 && ci < NLEAF) {
            const float4* yr = (const float4*)(Y + (size_t)ci * DIM);
            float4 ya = yr[lane * 2], yb = yr[lane * 2 + 1];
            float s = xa.x*ya.x + xa.y*ya.y + xa.z*ya.z + xa.w*ya.w
                    + xb.x*yb.x + xb.y*yb.y + xb.z*yb.z + xb.w*yb.w;
            #pragma unroll
            for (int o = 16; o > 0; o >>= 1) s += __shfl_down_sync(FULL, s, o);
            s = __shfl_sync(FULL, s, 0);
            float y2 = g_y2[ci];
            float sq    = fmaxf(x2 + y2 - 2.0f * s, 0.0f);
            float denom = fmaxf((1.0f - x2) * (1.0f - y2), EPSF);
            float arg   = fmaxf(1.0f + 2.0f * sq / denom, 1.0f + EPSF);
            dist = acoshf(arg);
        } else ci = -1;
        if (lane == cc) { my_dist = dist; seli = ci; }
    }

    float dall[SHORTL]; int iall[SHORTL];
    for (int cc = 0; cc < SHORTL; cc++) {
        dall[cc] = __shfl_sync(FULL, my_dist, cc);
        iall[cc] = __shfl_sync(FULL, seli, cc);
    }
    for (int a2 = 1; a2 < SHORTL; a2++) {
        float dv = dall[a2]; int iv = iall[a2];
        int p = a2;
        while (p > 0 && (dall[p-1] > dv || (dall[p-1] == dv && iall[p-1] > iv))) {
            dall[p] = dall[p-1]; iall[p] = iall[p-1]; p--;
        }
        dall[p] = dv; iall[p] = iv;
    }

    if (lane == 0) {
        float score = dall[0];
        out[row] = score;
        if (out_size >= 2 * BATCH)
            out[BATCH + row] = (score > thr_p[0]) ? 1.0f : 0.0f;
        if (out_size >= 7 * BATCH) {
            #pragma unroll
            for (int j = 0; j < 5; j++) {
                int ci = iall[j];
                out[2 * BATCH + (size_t)row * 5 + j] = (float)((ci >= 0) ? ids[ci] : 0);
            }
        }
    }
}

// ---------------------------------------------------------------------------
extern "C" void kernel_launch(void* const* d_in, const int* in_sizes, int n_in,
                              void* d_out, int out_size) {
    const float* X   = (const float*)d_in[0];
    const float* Y   = (const float*)d_in[1];
    const int*   ids = (const int*)d_in[2];
    const float* thr = (const float*)d_in[3];
    float* out = (float*)d_out;

    cudaFuncSetAttribute(main_kernel, cudaFuncAttributeMaxDynamicSharedMemorySize,
                         SMEM_TOTAL);

    int prep_warps = BATCH + NLEAF;
    prep_kernel<<<(prep_warps + 7) / 8, 256>>>(X, Y);

    main_kernel<<<dim3(BATCH / 128, NCHUNK), 256, SMEM_TOTAL>>>();

    merge_kernel<<<BATCH / 8, 256>>>(X, Y, ids, thr, out, out_size);
}

// round 15
// speedup vs baseline: 1.1913x; 1.0246x over previous
#include <cuda_runtime.h>
#include <cuda_bf16.h>
#include <cstdint>
#include <math.h>

#define BATCH   4096
#define NLEAF   50000
#define DIM     256
#define CHUNKL  5556
#define NCHUNK  9
#define NTILES  44
#define EPSF    1e-7f
#define SHORTL  16
#define NSLOT   5
#define NCANDR  (NCHUNK * NSLOT * 2)   // 90 per row

// smem: 2 stages of {Xbf, Ybf} (each mat 128 rows x 144B pitch, 128B data).
// f32 key-dump buffer overlays STAGE 1 ONLY plus a dedicated extension, so
// stage 0 stays live across the epilogue -> next tile's first chunk can be
// prefetched during kc=3 and remain in flight through dump+scan.
#define PITCH    144
#define MATB     (128 * PITCH)         // 18432
#define STAGEB   (2 * MATB)            // 36864
#define DPITCH   132                   // dump pitch in floats
#define DUMPB    (128 * DPITCH * 4)    // 67584
#define OFF_DUMP STAGEB                // dump = stage1 (36864B) + ext (30720B)
#define OFF_SCL  (OFF_DUMP + DUMPB)    // 104448
#define SMEM_TOTAL (OFF_SCL + 128 * 8) // 105472 -> 2 CTAs/SM

__device__ float g_x2[BATCH];
__device__ float g_y2[NLEAF];
__device__ float2 g_aff[NLEAF];        // (inv, y2*inv)
__device__ __align__(16) __nv_bfloat16 g_Xb[(size_t)BATCH * DIM];
__device__ __align__(16) __nv_bfloat16 g_Yb[(size_t)NLEAF * DIM];   // -2*inv*y
__device__ float g_cval[(size_t)NCHUNK * BATCH * NSLOT * 2];
__device__ int   g_cidx[(size_t)NCHUNK * BATCH * NSLOT * 2];

__device__ __forceinline__ uint32_t smem_to_u32(const void* p) {
    uint32_t a;
    asm("{ .reg .u64 t; cvta.to.shared.u64 t, %1; cvt.u32.u64 %0, t; }" : "=r"(a) : "l"(p));
    return a;
}
#define LDSM_X4(r, addr) \
    asm volatile("ldmatrix.sync.aligned.m8n8.x4.shared.b16 {%0,%1,%2,%3}, [%4];" \
        : "=r"((r)[0]), "=r"((r)[1]), "=r"((r)[2]), "=r"((r)[3]) : "r"(addr))
#define MMA16816(c, a, b0, b1) \
    asm volatile("mma.sync.aligned.m16n8k16.row.col.f32.bf16.bf16.f32 " \
        "{%0,%1,%2,%3},{%4,%5,%6,%7},{%8,%9},{%0,%1,%2,%3};" \
        : "+f"((c)[0]), "+f"((c)[1]), "+f"((c)[2]), "+f"((c)[3]) \
        : "r"((a)[0]), "r"((a)[1]), "r"((a)[2]), "r"((a)[3]), "r"(b0), "r"(b1))
#define CP_WAIT(n) asm volatile("cp.async.wait_group %0;" :: "n"(n) : "memory")

__device__ __forceinline__ unsigned bfu(__nv_bfloat16 h) {
    return (unsigned)__bfloat16_as_ushort(h);
}

// ---------------- Kernel 1: norms + single bf16 quantization --------------
// X rows: bf16(x).  Y rows: bf16(-2*inv*y), inv = 1/(1-y2).
// key = dot + x2*inv[col] + y2inv[col]: monotone hyperbolic rank key.
__global__ void prep_kernel(const float* __restrict__ X, const float* __restrict__ Y) {
    int warp = (blockIdx.x * blockDim.x + threadIdx.x) >> 5;
    int lane = threadIdx.x & 31;
    if (warp >= BATCH + NLEAF) return;
    bool isX = warp < BATCH;
    int row = isX ? warp : warp - BATCH;
    const float* src = (isX ? X : Y) + (size_t)row * DIM;
    float4 a = ((const float4*)src)[lane * 2];
    float4 b = ((const float4*)src)[lane * 2 + 1];
    float v[8] = {a.x, a.y, a.z, a.w, b.x, b.y, b.z, b.w};
    float s = 0.0f;
    #pragma unroll
    for (int i = 0; i < 8; i++) s += v[i] * v[i];
    #pragma unroll
    for (int o = 16; o; o >>= 1) s += __shfl_xor_sync(0xffffffffu, s, o);

    float sc = 1.0f;
    __nv_bfloat16* dst;
    if (isX) {
        if (lane == 0) g_x2[row] = s;
        dst = g_Xb + (size_t)row * DIM;
    } else {
        float inv = 1.0f / (1.0f - s);
        if (lane == 0) {
            g_y2[row] = s;
            g_aff[row] = make_float2(inv, s * inv);
        }
        sc = -2.0f * inv;
        dst = g_Yb + (size_t)row * DIM;
    }
    unsigned w[4];
    #pragma unroll
    for (int i = 0; i < 4; i++) {
        __nv_bfloat16 h0 = __float2bfloat16(v[2*i] * sc);
        __nv_bfloat16 h1 = __float2bfloat16(v[2*i+1] * sc);
        w[i] = bfu(h0) | (bfu(h1) << 16);
    }
    ((uint4*)dst)[lane] = make_uint4(w[0], w[1], w[2], w[3]);
}

// cp.async one 64-element (128B) k-chunk of X and Y tiles into one smem stage.
__device__ __forceinline__ void issue_loads(uint32_t stg, int tid, int mrow0,
                                            int leaf0, int kc) {
    const int k0 = kc * 64;
    #pragma unroll
    for (int i = 0; i < 8; i++) {
        int u = tid + 256 * i;
        int mat = u >> 10;
        int rem = u & 1023;
        int row = rem >> 3;
        int col = rem & 7;
        uint32_t dst = stg + (uint32_t)mat * MATB + (uint32_t)row * PITCH
                     + (uint32_t)col * 16;
        const __nv_bfloat16* src;
        if (mat == 0) {
            src = g_Xb + (size_t)(mrow0 + row) * DIM + k0 + col * 8;
        } else {
            int leaf = leaf0 + row; if (leaf >= NLEAF) leaf = NLEAF - 1;
            src = g_Yb + (size_t)leaf * DIM + k0 + col * 8;
        }
        asm volatile("cp.async.cg.shared.global [%0], [%1], 16;"
                     :: "r"(dst), "l"(src) : "memory");
    }
    asm volatile("cp.async.commit_group;" ::: "memory");
}

// per-thread sorted top-NSLOT insert (rare path)
__device__ __forceinline__ void topk_insert(float* tv, int* ti, float key, int idx,
                                            float& worst) {
    tv[NSLOT - 1] = key; ti[NSLOT - 1] = idx;
    #pragma unroll
    for (int q = NSLOT - 1; q > 0; q--) {
        if (tv[q] < tv[q - 1]) {
            float fv = tv[q]; tv[q] = tv[q - 1]; tv[q - 1] = fv;
            int iv = ti[q]; ti[q] = ti[q - 1]; ti[q - 1] = iv;
        }
    }
    worst = tv[NSLOT - 1];
}

// ---------------- Kernel 2: single-pass bf16 mma.sync GEMM + fused top-5 --
// 256 threads = 8 warps (2m x 4n), warp tile 64x32, block tile 128x128, K=256.
__global__ void __launch_bounds__(256, 2) main_kernel() {
    extern __shared__ char smem[];
    const uint32_t sb = smem_to_u32(smem);
    const int tid = threadIdx.x, lane = tid & 31, w = tid >> 5;
    const int wm = w >> 2, wn = w & 3;
    const int mblk = blockIdx.x, chunk = blockIdx.y;
    const int mrow0 = mblk * 128;
    const int leaf_base = chunk * CHUNKL;
    int leaf_end = leaf_base + CHUNKL; if (leaf_end > NLEAF) leaf_end = NLEAF;

    const uint32_t aoff = (uint32_t)(wm * 64 + (lane & 15)) * PITCH
                        + ((lane >> 4) & 1) * 16;
    const uint32_t boff = (uint32_t)(wn * 32 + (lane & 7) + ((lane >> 4) & 1) * 8) * PITCH
                        + ((lane >> 3) & 1) * 16;

    // dump-phase row constants: x2 for the 8 rows this thread owns
    float x2r8[8];
    {
        const int rbase = mrow0 + wm * 64 + (lane >> 2);
        #pragma unroll
        for (int mi = 0; mi < 4; mi++) {
            x2r8[mi * 2]     = g_x2[rbase + mi * 16];
            x2r8[mi * 2 + 1] = g_x2[rbase + mi * 16 + 8];
        }
    }
    const uint32_t sSCL = sb + OFF_SCL;

    float tv[NSLOT]; int ti[NSLOT];
    #pragma unroll
    for (int q = 0; q < NSLOT; q++) { tv[q] = INFINITY; ti[q] = -1; }
    float worst = INFINITY;

    // prologue: chunk(0,0) -> stage0
    issue_loads(sb, tid, mrow0, leaf_base, 0);

    for (int t = 0; t < NTILES; t++) {
        const int leaf0 = leaf_base + t * 128;
        // stage this tile's per-col affine terms (read at this tile's dump;
        // prev dump's read of sSCL is ordered by the pre-scan sync)
        if (tid < 128) {
            int leaf = leaf0 + tid; if (leaf >= NLEAF) leaf = NLEAF - 1;
            float2 af = g_aff[leaf];
            asm volatile("st.shared.v2.f32 [%0], {%1,%2};"
                         :: "r"(sSCL + tid * 8), "f"(af.x), "f"(af.y) : "memory");
        }

        float c[4][4][4];
        #pragma unroll
        for (int mi = 0; mi < 4; mi++)
            #pragma unroll
            for (int ni = 0; ni < 4; ni++)
                #pragma unroll
                for (int e = 0; e < 4; e++) c[mi][ni][e] = 0.0f;

        #pragma unroll
        for (int kc = 0; kc < 4; kc++) {
            CP_WAIT(0);               // chunk(t,kc) resident in stage kc&1
            __syncthreads();          // all warps done reading the dst stage
            if (kc < 3) {
                issue_loads(sb + (uint32_t)((kc + 1) & 1) * STAGEB,
                            tid, mrow0, leaf0, kc + 1);
            } else if (t + 1 < NTILES) {
                // cross-tile prefetch into stage0 (not overlaid by dump)
                issue_loads(sb, tid, mrow0, leaf0 + 128, 0);
            }

            const uint32_t stg = sb + (uint32_t)(kc & 1) * STAGEB;
            #pragma unroll
            for (int ks = 0; ks < 4; ks++) {
                uint32_t a[4][4], b[2][4];
                #pragma unroll
                for (int mi = 0; mi < 4; mi++)
                    LDSM_X4(a[mi], stg + (uint32_t)(mi * 16) * PITCH + ks * 32 + aoff);
                #pragma unroll
                for (int nb = 0; nb < 2; nb++)
                    LDSM_X4(b[nb], stg + MATB + (uint32_t)(nb * 16) * PITCH + ks * 32 + boff);
                #pragma unroll
                for (int mi = 0; mi < 4; mi++) {
                    #pragma unroll
                    for (int nb = 0; nb < 2; nb++) {
                        MMA16816(c[mi][2 * nb],     a[mi], b[nb][0], b[nb][1]);
                        MMA16816(c[mi][2 * nb + 1], a[mi], b[nb][2], b[nb][3]);
                    }
                }
            }
        }
        __syncthreads();   // all warps done reading stage1 before dump overlays it

        // dump: finalize keys (dot + x2*inv + y2inv, no clamp: monotone) into
        // stage1 + extension (stage0 holds the in-flight prefetch)
        {
            const int r0 = wm * 64 + (lane >> 2);
            const int c0 = wn * 32 + 2 * (lane & 3);
            #pragma unroll
            for (int ni = 0; ni < 4; ni++) {
                int cA = c0 + ni * 8;
                float2 sA, sB;
                asm volatile("ld.shared.v2.f32 {%0,%1}, [%2];"
                             : "=f"(sA.x), "=f"(sA.y) : "r"(sSCL + cA * 8));
                asm volatile("ld.shared.v2.f32 {%0,%1}, [%2];"
                             : "=f"(sB.x), "=f"(sB.y) : "r"(sSCL + (cA + 1) * 8));
                #pragma unroll
                for (int mi = 0; mi < 4; mi++) {
                    float k0 = fmaf(x2r8[2*mi],   sA.x, sA.y) + c[mi][ni][0];
                    float k1 = fmaf(x2r8[2*mi],   sB.x, sB.y) + c[mi][ni][1];
                    float k2 = fmaf(x2r8[2*mi+1], sA.x, sA.y) + c[mi][ni][2];
                    float k3 = fmaf(x2r8[2*mi+1], sB.x, sB.y) + c[mi][ni][3];
                    uint32_t a0 = sb + OFF_DUMP
                                + (uint32_t)((r0 + mi * 16) * DPITCH + cA) * 4;
                    asm volatile("st.shared.v2.f32 [%0], {%1,%2};"
                                 :: "r"(a0), "f"(k0), "f"(k1) : "memory");
                    asm volatile("st.shared.v2.f32 [%0], {%1,%2};"
                                 :: "r"(a0 + 8 * DPITCH * 4), "f"(k2), "f"(k3) : "memory");
                }
            }
        }
        __syncthreads();

        // scan: thread owns (row = tid&127, half = tid>>7): top-5 over 64 keys
        // with a min4 pre-filter (rare-path insert only).
        {
            const int half = tid >> 7;
            const int nvalid = leaf_end - leaf0;
            const uint32_t rb = sb + OFF_DUMP + (uint32_t)(tid & 127) * (DPITCH * 4)
                              + half * 256;
            if (nvalid >= 128) {
                #pragma unroll
                for (int j4 = 0; j4 < 16; j4++) {
                    float v0, v1, v2, v3;
                    asm volatile("ld.shared.v4.f32 {%0,%1,%2,%3}, [%4];"
                                 : "=f"(v0), "=f"(v1), "=f"(v2), "=f"(v3)
                                 : "r"(rb + j4 * 16));
                    float m4 = fminf(fminf(v0, v1), fminf(v2, v3));
                    if (m4 < worst) {
                        int colb = leaf0 + half * 64 + j4 * 4;
                        if (v0 < worst) topk_insert(tv, ti, v0, colb + 0, worst);
                        if (v1 < worst) topk_insert(tv, ti, v1, colb + 1, worst);
                        if (v2 < worst) topk_insert(tv, ti, v2, colb + 2, worst);
                        if (v3 < worst) topk_insert(tv, ti, v3, colb + 3, worst);
                    }
                }
            } else {
                for (int j4 = 0; j4 < 16; j4++) {
                    float v0, v1, v2, v3;
                    asm volatile("ld.shared.v4.f32 {%0,%1,%2,%3}, [%4];"
                                 : "=f"(v0), "=f"(v1), "=f"(v2), "=f"(v3)
                                 : "r"(rb + j4 * 16));
                    float vv[4] = {v0, v1, v2, v3};
                    #pragma unroll
                    for (int e = 0; e < 4; e++) {
                        int col = half * 64 + j4 * 4 + e;
                        if (col < nvalid && vv[e] < worst)
                            topk_insert(tv, ti, vv[e], leaf0 + col, worst);
                    }
                }
            }
        }
        // no post-scan sync: next tile's kc0 CP_WAIT(0)+__syncthreads orders
        // this scan before any write to the scanned region (stage1).
    }

    const int grow_s = mrow0 + (tid & 127);
    const size_t cb = (((size_t)chunk * BATCH + grow_s) * 2 + (tid >> 7)) * NSLOT;
    #pragma unroll
    for (int q = 0; q < NSLOT; q++) { g_cval[cb + q] = tv[q]; g_cidx[cb + q] = ti[q]; }
}

// ---------------- Kernel 3: merge 90 cands -> top-16, exact re-rank -------
__global__ void merge_kernel(const float* __restrict__ X, const float* __restrict__ Y,
                             const int* __restrict__ ids, const float* __restrict__ thr_p,
                             float* __restrict__ out, int out_size) {
    const int lane = threadIdx.x & 31;
    const int row = blockIdx.x * 8 + (threadIdx.x >> 5);
    if (row >= BATCH) return;
    const unsigned FULL = 0xffffffffu;

    float lv[SHORTL]; int li[SHORTL];
    #pragma unroll
    for (int s = 0; s < SHORTL; s++) { lv[s] = INFINITY; li[s] = 0x7fffffff; }
    const int RSTRIDE = NSLOT * 2;   // 10 candidates per (chunk,row)
    for (int f = lane; f < NCANDR; f += 32) {
        int ch = f / RSTRIDE, r = f - ch * RSTRIDE;
        size_t a = ((size_t)ch * BATCH + row) * RSTRIDE + r;
        float v = g_cval[a];
        if (v < lv[SHORTL - 1]) {
            int ix = g_cidx[a];
            if (ix < 0) continue;
            int p = SHORTL - 1;
            while (p > 0 && (lv[p-1] > v || (lv[p-1] == v && li[p-1] > ix))) {
                lv[p] = lv[p-1]; li[p] = li[p-1]; p--;
            }
            lv[p] = v; li[p] = ix;
        }
    }

    int head = 0, seli = -1;
    for (int r = 0; r < SHORTL; r++) {
        float bv = (head < SHORTL) ? lv[head] : INFINITY;
        int   bi = (head < SHORTL) ? li[head] : 0x7fffffff;
        int   bl = lane;
        #pragma unroll
        for (int o = 16; o > 0; o >>= 1) {
            float ov = __shfl_down_sync(FULL, bv, o);
            int oi = __shfl_down_sync(FULL, bi, o);
            int ol = __shfl_down_sync(FULL, bl, o);
            if (ov < bv || (ov == bv && oi < bi)) { bv = ov; bi = oi; bl = ol; }
        }
        bi = __shfl_sync(FULL, bi, 0);
        bl = __shfl_sync(FULL, bl, 0);
        if (lane == r) seli = bi;
        if (lane == bl) head++;
    }

    float x2 = g_x2[row];
    const float4* xr = (const float4*)(X + (size_t)row * DIM);
    float4 xa = xr[lane * 2], xb = xr[lane * 2 + 1];
    float my_dist = INFINITY;
    for (int cc = 0; cc < SHORTL; cc++) {
        int ci = __shfl_sync(FULL, seli, cc);
        float dist = INFINITY;
        if (ci >= 0 && ci < NLEAF) {
            const float4* yr = (const float4*)(Y + (size_t)ci * DIM);
            float4 ya = yr[lane * 2], yb = yr[lane * 2 + 1];
            float s = xa.x*ya.x + xa.y*ya.y + xa.z*ya.z + xa.w*ya.w
                    + xb.x*yb.x + xb.y*yb.y + xb.z*yb.z + xb.w*yb.w;
            #pragma unroll
            for (int o = 16; o > 0; o >>= 1) s += __shfl_down_sync(FULL, s, o);
            s = __shfl_sync(FULL, s, 0);
            float y2 = g_y2[ci];
            float sq    = fmaxf(x2 + y2 - 2.0f * s, 0.0f);
            float denom = fmaxf((1.0f - x2) * (1.0f - y2), EPSF);
            float arg   = fmaxf(1.0f + 2.0f * sq / denom, 1.0f + EPSF);
            dist = acoshf(arg);
        } else ci = -1;
        if (lane == cc) { my_dist = dist; seli = ci; }
    }

    float dall[SHORTL]; int iall[SHORTL];
    for (int cc = 0; cc < SHORTL; cc++) {
        dall[cc] = __shfl_sync(FULL, my_dist, cc);
        iall[cc] = __shfl_sync(FULL, seli, cc);
    }
    for (int a2 = 1; a2 < SHORTL; a2++) {
        float dv = dall[a2]; int iv = iall[a2];
        int p = a2;
        while (p > 0 && (dall[p-1] > dv || (dall[p-1] == dv && iall[p-1] > iv))) {
            dall[p] = dall[p-1]; iall[p] = iall[p-1]; p--;
        }
        dall[p] = dv; iall[p] = iv;
    }

    if (lane == 0) {
        float score = dall[0];
        out[row] = score;
        if (out_size >= 2 * BATCH)
            out[BATCH + row] = (score > thr_p[0]) ? 1.0f : 0.0f;
        if (out_size >= 7 * BATCH) {
            #pragma unroll
            for (int j = 0; j < 5; j++) {
                int ci = iall[j];
                out[2 * BATCH + (size_t)row * 5 + j] = (float)((ci >= 0) ? ids[ci] : 0);
            }
        }
    }
}

// ---------------------------------------------------------------------------
extern "C" void kernel_launch(void* const* d_in, const int* in_sizes, int n_in,
                              void* d_out, int out_size) {
    const float* X   = (const float*)d_in[0];
    const float* Y   = (const float*)d_in[1];
    const int*   ids = (const int*)d_in[2];
    const float* thr = (const float*)d_in[3];
    float* out = (float*)d_out;

    cudaFuncSetAttribute(main_kernel, cudaFuncAttributeMaxDynamicSharedMemorySize,
                         SMEM_TOTAL);

    int prep_warps = BATCH + NLEAF;
    prep_kernel<<<(prep_warps + 7) / 8, 256>>>(X, Y);

    main_kernel<<<dim3(BATCH / 128, NCHUNK), 256, SMEM_TOTAL>>>();

    merge_kernel<<<BATCH / 8, 256>>>(X, Y, ids, thr, out, out_size);
}